// round 12
// baseline (speedup 1.0000x reference)
#include <cuda_runtime.h>
#include <cstddef>

#define N_ROWS 4096
#define CH     256
#define NC     1000
#define NTILE  10      // upper-triangle 64x64 tiles of 256x256
#define NSPLIT 32      // K-splits of depth 128 over K=4096

// ---- scratch (static device globals; no runtime allocation) ----
__device__ float g_invn[N_ROWS];
__device__ float g_xn[N_ROWS * CH];                // D^-1 X (normalized rows)
__device__ float g_G[CH * CH];                     // full (mirrored) gram
__device__ float g_part[NTILE * NSPLIT * 64 * 64]; // 5.2 MB partial tiles
__device__ float g_s[NC * CH];                     // per-class sum invn_r * x_r
__device__ float g_t[NC * CH];                     // per-class sum x_r
__device__ float g_counts[NC];

__constant__ int c_ti[NTILE] = {0,0,0,0,1,1,1,2,2,3};
__constant__ int c_tj[NTILE] = {0,1,2,3,1,2,3,2,3,3};

// ---------------------------------------------------------------
// K1: prep — norms (+ write normalized rows) + zero class accumulators
// ---------------------------------------------------------------
__global__ void k_prep(const float* __restrict__ x) {
    int b = blockIdx.x;
    int tid = threadIdx.x;
    if (b < 512) {
        int warp = ((b << 8) + tid) >> 5;       // 0..4095
        int lane = tid & 31;
        const float4* p = (const float4*)(x + (size_t)warp * CH);
        float4 v0 = p[lane];
        float4 v1 = p[lane + 32];
        float ss = v0.x * v0.x + v0.y * v0.y + v0.z * v0.z + v0.w * v0.w
                 + v1.x * v1.x + v1.y * v1.y + v1.z * v1.z + v1.w * v1.w;
#pragma unroll
        for (int off = 16; off; off >>= 1)
            ss += __shfl_xor_sync(0xffffffffu, ss, off);
        float inv = rsqrtf(ss);
        float4* xn4 = (float4*)(g_xn + (size_t)warp * CH);
        xn4[lane]      = make_float4(v0.x * inv, v0.y * inv, v0.z * inv, v0.w * inv);
        xn4[lane + 32] = make_float4(v1.x * inv, v1.y * inv, v1.z * inv, v1.w * inv);
        if (lane == 0) g_invn[warp] = inv;
    } else if (b < 762) {
        ((float4*)g_s)[(b - 512) * 256 + tid] = make_float4(0.f, 0.f, 0.f, 0.f);
    } else if (b < 1012) {
        ((float4*)g_t)[(b - 762) * 256 + tid] = make_float4(0.f, 0.f, 0.f, 0.f);
    } else {
        for (int i = tid; i < NC; i += 256) g_counts[i] = 0.0f;
    }
}

// ---------------------------------------------------------------
// K2: fused gram-partials (double-buffered) + (argmax -> class scatter).
//  b in [0,320):       G-partial = Xn^T X over 64x64 tile, K-depth 128.
//                      smem double buffering: one barrier per 16-k chunk,
//                      next chunk's LDGs issued before current compute.
//  b in [320,320+512): warp-per-row argmax + scatter into g_s / g_t.
// ---------------------------------------------------------------
__global__ void k_fused(const float* __restrict__ x,
                        const float* __restrict__ lg) {
    __shared__ float smem[4096];   // 2 x (As[1024] | Bs[1024])
    int b = blockIdx.x;
    int tid = threadIdx.x;

    if (b < NTILE * NSPLIT) {
        int tile = b >> 5;           // 0..9
        int k0 = (b & 31) * 128;     // split * 128
        int i0 = c_ti[tile] * 64, j0 = c_tj[tile] * 64;
        int tx = tid & 15, ty = tid >> 4;

        // per-chunk load indices (4 elements each for As and Bs)
        int kl_[4], col_[4];
#pragma unroll
        for (int l = 0; l < 4; l++) {
            int idx = tid + l * 256;
            kl_[l] = idx >> 6;
            col_[l] = idx & 63;
        }

        float ra[4], rb[4];
        // prologue: load chunk 0 into registers
#pragma unroll
        for (int l = 0; l < 4; l++) {
            int k = k0 + kl_[l];
            ra[l] = g_xn[(size_t)k * CH + i0 + col_[l]];
            rb[l] = x  [(size_t)k * CH + j0 + col_[l]];
        }
        {
            float* As = smem;
            float* Bs = smem + 1024;
#pragma unroll
            for (int l = 0; l < 4; l++) {
                As[kl_[l] * 64 + col_[l]] = ra[l];
                Bs[kl_[l] * 64 + col_[l]] = rb[l];
            }
        }
        __syncthreads();

        float acc[4][4] = {};
#pragma unroll
        for (int c = 0; c < 8; c++) {
            // issue next chunk's global loads first (hide latency behind FMAs)
            if (c < 7) {
#pragma unroll
                for (int l = 0; l < 4; l++) {
                    int k = k0 + (c + 1) * 16 + kl_[l];
                    ra[l] = g_xn[(size_t)k * CH + i0 + col_[l]];
                    rb[l] = x  [(size_t)k * CH + j0 + col_[l]];
                }
            }
            const float4* As4 = (const float4*)(smem + (c & 1) * 2048);
            const float4* Bs4 = (const float4*)(smem + (c & 1) * 2048 + 1024);
#pragma unroll
            for (int kl = 0; kl < 16; kl++) {
                float4 a = As4[kl * 16 + ty];
                float4 bb = Bs4[kl * 16 + tx];
                acc[0][0] += a.x * bb.x; acc[0][1] += a.x * bb.y;
                acc[0][2] += a.x * bb.z; acc[0][3] += a.x * bb.w;
                acc[1][0] += a.y * bb.x; acc[1][1] += a.y * bb.y;
                acc[1][2] += a.y * bb.z; acc[1][3] += a.y * bb.w;
                acc[2][0] += a.z * bb.x; acc[2][1] += a.z * bb.y;
                acc[2][2] += a.z * bb.z; acc[2][3] += a.z * bb.w;
                acc[3][0] += a.w * bb.x; acc[3][1] += a.w * bb.y;
                acc[3][2] += a.w * bb.z; acc[3][3] += a.w * bb.w;
            }
            if (c < 7) {
                float* As = smem + ((c + 1) & 1) * 2048;
                float* Bs = As + 1024;
#pragma unroll
                for (int l = 0; l < 4; l++) {
                    As[kl_[l] * 64 + col_[l]] = ra[l];
                    Bs[kl_[l] * 64 + col_[l]] = rb[l];
                }
            }
            __syncthreads();
        }
        // store partial tile: coalesced float4 per (u-row)
        float4* p4 = (float4*)(g_part + (size_t)b * 4096);
#pragma unroll
        for (int u = 0; u < 4; u++)
            p4[(ty * 4 + u) * 16 + tx] =
                make_float4(acc[u][0], acc[u][1], acc[u][2], acc[u][3]);
    } else {
        // ---- warp-per-row argmax + scatter, 8 rows per block ----
        int row = ((b - NTILE * NSPLIT) << 3) + (tid >> 5);
        int lane = tid & 31;
        const float4* p = (const float4*)(lg + (size_t)row * NC);  // 250 float4
        float best = -3.4e38f;
        int   bi = 0;
#pragma unroll
        for (int i = 0; i < 8; i++) {
            int idx = lane + (i << 5);
            if (idx < 250) {
                float4 v = p[idx];
                int c = idx << 2;
                if (v.x > best) { best = v.x; bi = c; }
                if (v.y > best) { best = v.y; bi = c + 1; }
                if (v.z > best) { best = v.z; bi = c + 2; }
                if (v.w > best) { best = v.w; bi = c + 3; }
            }
        }
#pragma unroll
        for (int off = 16; off; off >>= 1) {
            float ov = __shfl_xor_sync(0xffffffffu, best, off);
            int   oi = __shfl_xor_sync(0xffffffffu, bi,   off);
            if (ov > best || (ov == best && oi < bi)) { best = ov; bi = oi; }
        }
        int cls = bi;
        float inv = g_invn[row];
        const float4* px = (const float4*)(x + (size_t)row * CH);
#pragma unroll
        for (int j = 0; j < 2; j++) {
            int idx4 = lane + (j << 5);           // 0..63
            float4 xv = px[idx4];
            int base = cls * CH + (idx4 << 2);
            atomicAdd(&g_s[base + 0], xv.x * inv);
            atomicAdd(&g_s[base + 1], xv.y * inv);
            atomicAdd(&g_s[base + 2], xv.z * inv);
            atomicAdd(&g_s[base + 3], xv.w * inv);
            atomicAdd(&g_t[base + 0], xv.x);
            atomicAdd(&g_t[base + 1], xv.y);
            atomicAdd(&g_t[base + 2], xv.z);
            atomicAdd(&g_t[base + 3], xv.w);
        }
        if (lane == 0) atomicAdd(&g_counts[cls], 1.0f);
    }
}

// ---------------------------------------------------------------
// K3: reduce partial gram tiles -> g_G, with symmetric mirror.
// ---------------------------------------------------------------
__global__ void k_redG() {
    int idx = blockIdx.x * 256 + threadIdx.x;   // 0..10239
    int tile = idx >> 10;
    int p4   = idx & 1023;                      // float4 index in 64x64 tile
    int i0 = c_ti[tile] * 64, j0 = c_tj[tile] * 64;

    const float4* part4 = (const float4*)g_part;
    float4 sum = make_float4(0.f, 0.f, 0.f, 0.f);
#pragma unroll 8
    for (int s = 0; s < NSPLIT; s++) {
        float4 v = part4[(size_t)((tile << 5) + s) * 1024 + p4];
        sum.x += v.x; sum.y += v.y; sum.z += v.z; sum.w += v.w;
    }
    int il = p4 >> 4;              // 0..63
    int jb = (p4 & 15) << 2;       // 0,4,..,60
    int i = i0 + il, j = j0 + jb;
    ((float4*)g_G)[(i * CH + j) >> 2] = sum;
    if (i0 != j0) {
        g_G[(j + 0) * CH + i] = sum.x;
        g_G[(j + 1) * CH + i] = sum.y;
        g_G[(j + 2) * CH + i] = sum.z;
        g_G[(j + 3) * CH + i] = sum.w;
    }
}

// ---------------------------------------------------------------
// K4: prototypes: proto_c = (s_c @ G + t_c) / count  (0 if count==0)
// 250 blocks x 1024 threads; thread = (cgrp 0..3, k-quarter sub 0..3, col4).
// ---------------------------------------------------------------
__global__ void __launch_bounds__(1024) k_proto(float* __restrict__ proto) {
    __shared__ float  s_sm[4 * 256];
    __shared__ float4 red[3 * 4 * 64];
    int c0 = blockIdx.x * 4;
    int tid = threadIdx.x;
    int cgrp = tid >> 8;          // 0..3  class within block
    int sub  = (tid >> 6) & 3;    // k-quarter
    int col4 = tid & 63;          // float4 column group

    s_sm[tid] = g_s[(size_t)c0 * CH + tid];
    __syncthreads();

    const float4* Gp = (const float4*)g_G + (size_t)(sub * 64) * 64 + col4;
    const float*  sr = s_sm + cgrp * 256 + sub * 64;
    float4 acc = make_float4(0.f, 0.f, 0.f, 0.f);
#pragma unroll
    for (int kb = 0; kb < 64; kb += 8) {
        float4 g0 = Gp[(kb + 0) * 64];
        float4 g1 = Gp[(kb + 1) * 64];
        float4 g2 = Gp[(kb + 2) * 64];
        float4 g3 = Gp[(kb + 3) * 64];
        float4 g4 = Gp[(kb + 4) * 64];
        float4 g5 = Gp[(kb + 5) * 64];
        float4 g6 = Gp[(kb + 6) * 64];
        float4 g7 = Gp[(kb + 7) * 64];
        float s0 = sr[kb + 0], s1 = sr[kb + 1], s2 = sr[kb + 2], s3 = sr[kb + 3];
        float s4 = sr[kb + 4], s5 = sr[kb + 5], s6 = sr[kb + 6], s7 = sr[kb + 7];
        acc.x += s0 * g0.x; acc.y += s0 * g0.y; acc.z += s0 * g0.z; acc.w += s0 * g0.w;
        acc.x += s1 * g1.x; acc.y += s1 * g1.y; acc.z += s1 * g1.z; acc.w += s1 * g1.w;
        acc.x += s2 * g2.x; acc.y += s2 * g2.y; acc.z += s2 * g2.z; acc.w += s2 * g2.w;
        acc.x += s3 * g3.x; acc.y += s3 * g3.y; acc.z += s3 * g3.z; acc.w += s3 * g3.w;
        acc.x += s4 * g4.x; acc.y += s4 * g4.y; acc.z += s4 * g4.z; acc.w += s4 * g4.w;
        acc.x += s5 * g5.x; acc.y += s5 * g5.y; acc.z += s5 * g5.z; acc.w += s5 * g5.w;
        acc.x += s6 * g6.x; acc.y += s6 * g6.y; acc.z += s6 * g6.z; acc.w += s6 * g6.w;
        acc.x += s7 * g7.x; acc.y += s7 * g7.y; acc.z += s7 * g7.z; acc.w += s7 * g7.w;
    }

    if (sub > 0) red[(sub - 1) * 256 + cgrp * 64 + col4] = acc;
    __syncthreads();
    if (sub == 0) {
        float4 o0 = red[0 * 256 + cgrp * 64 + col4];
        float4 o1 = red[1 * 256 + cgrp * 64 + col4];
        float4 o2 = red[2 * 256 + cgrp * 64 + col4];
        acc.x += o0.x + o1.x + o2.x;
        acc.y += o0.y + o1.y + o2.y;
        acc.z += o0.z + o1.z + o2.z;
        acc.w += o0.w + o1.w + o2.w;

        int cls = c0 + cgrp;
        float cnt = g_counts[cls];
        float4 tv = ((const float4*)g_t)[(size_t)cls * 64 + col4];
        float4 v = make_float4(0.f, 0.f, 0.f, 0.f);
        if (cnt > 0.0f) {
            float rc = 1.0f / cnt;
            v = make_float4((acc.x + tv.x) * rc, (acc.y + tv.y) * rc,
                            (acc.z + tv.z) * rc, (acc.w + tv.w) * rc);
        }
        ((float4*)proto)[(size_t)cls * 64 + col4] = v;
    }
}

// ---------------------------------------------------------------
// K5: inter[i][j][:] = proto[j] - proto[i]   (1.02 GB, write-bound)
// ---------------------------------------------------------------
__global__ void k_inter(const float* __restrict__ proto, float* __restrict__ inter) {
    __shared__ float4 pi[16][64];
    __shared__ float4 pj[16][64];
    int i0 = blockIdx.y * 16, j0 = blockIdx.x * 16;
    int tid = threadIdx.x;               // 256 threads

    const float4* p4 = (const float4*)proto;
#pragma unroll
    for (int l = 0; l < 4; l++) {
        int idx = tid + l * 256;         // 0..1023
        int r = idx >> 6, d = idx & 63;
        int gi = i0 + r, gj = j0 + r;
        pi[r][d] = (gi < NC) ? p4[gi * 64 + d] : make_float4(0.f, 0.f, 0.f, 0.f);
        pj[r][d] = (gj < NC) ? p4[gj * 64 + d] : make_float4(0.f, 0.f, 0.f, 0.f);
    }
    __syncthreads();

    int d = tid & 63;
    int p0 = tid >> 6;                   // 0..3
    float4* o4 = (float4*)inter;

    if (i0 + 16 <= NC && j0 + 16 <= NC) {
#pragma unroll 8
        for (int p = p0; p < 256; p += 4) {
            int il = p >> 4, jl = p & 15;
            float4 a = pj[jl][d];
            float4 bv = pi[il][d];
            float4 v = make_float4(a.x - bv.x, a.y - bv.y, a.z - bv.z, a.w - bv.w);
            __stcs(&o4[((size_t)(i0 + il) * NC + (j0 + jl)) * 64 + d], v);
        }
    } else {
        for (int p = p0; p < 256; p += 4) {
            int il = p >> 4, jl = p & 15;
            int i = i0 + il, j = j0 + jl;
            if (i < NC && j < NC) {
                float4 a = pj[jl][d];
                float4 bv = pi[il][d];
                float4 v = make_float4(a.x - bv.x, a.y - bv.y, a.z - bv.z, a.w - bv.w);
                __stcs(&o4[((size_t)i * NC + j) * 64 + d], v);
            }
        }
    }
}

// ---------------------------------------------------------------
extern "C" void kernel_launch(void* const* d_in, const int* in_sizes, int n_in,
                              void* d_out, int out_size) {
    const float* x  = (const float*)d_in[0];   // [4096, 256]
    const float* lg = (const float*)d_in[1];   // [4096, 1000]
    float* out   = (float*)d_out;
    float* proto = out;                         // [1000, 256]
    float* inter = out + (size_t)NC * CH;       // [1000, 1000, 256]

    k_prep <<<1013, 256>>>(x);
    k_fused<<<NTILE * NSPLIT + 512, 256>>>(x, lg);
    k_redG <<<40, 256>>>();
    k_proto<<<250, 1024>>>(proto);
    k_inter<<<dim3(63, 63), 256>>>(proto, inter);
}

// round 13
// speedup vs baseline: 1.0186x; 1.0186x over previous
#include <cuda_runtime.h>
#include <cstddef>

#define N_ROWS 4096
#define CH     256
#define NC     1000
#define NTILE  10      // upper-triangle 64x64 tiles of 256x256
#define NSPLIT 32      // K-splits of depth 128 over K=4096

// ---- scratch (static device globals; no runtime allocation) ----
__device__ float g_invn[N_ROWS];
__device__ float g_xn[N_ROWS * CH];                // D^-1 X (normalized rows)
__device__ float g_G[CH * CH];                     // full (mirrored) gram
__device__ float g_part[NTILE * NSPLIT * 64 * 64]; // 5.2 MB partial tiles
__device__ float g_s[NC * CH];                     // per-class sum invn_r * x_r
__device__ float g_t[NC * CH];                     // per-class sum x_r
__device__ float g_counts[NC];
__device__ unsigned int g_flag;                    // redG-done counter

__constant__ int c_ti[NTILE] = {0,0,0,0,1,1,1,2,2,3};
__constant__ int c_tj[NTILE] = {0,1,2,3,1,2,3,2,3,3};

// ---------------------------------------------------------------
// K1: prep — norms (+ write normalized rows) + zero class accumulators
// ---------------------------------------------------------------
__global__ void k_prep(const float* __restrict__ x) {
    int b = blockIdx.x;
    int tid = threadIdx.x;
    if (b < 512) {
        int warp = ((b << 8) + tid) >> 5;       // 0..4095
        int lane = tid & 31;
        const float4* p = (const float4*)(x + (size_t)warp * CH);
        float4 v0 = p[lane];
        float4 v1 = p[lane + 32];
        float ss = v0.x * v0.x + v0.y * v0.y + v0.z * v0.z + v0.w * v0.w
                 + v1.x * v1.x + v1.y * v1.y + v1.z * v1.z + v1.w * v1.w;
#pragma unroll
        for (int off = 16; off; off >>= 1)
            ss += __shfl_xor_sync(0xffffffffu, ss, off);
        float inv = rsqrtf(ss);
        float4* xn4 = (float4*)(g_xn + (size_t)warp * CH);
        xn4[lane]      = make_float4(v0.x * inv, v0.y * inv, v0.z * inv, v0.w * inv);
        xn4[lane + 32] = make_float4(v1.x * inv, v1.y * inv, v1.z * inv, v1.w * inv);
        if (lane == 0) g_invn[warp] = inv;
    } else if (b < 762) {
        ((float4*)g_s)[(b - 512) * 256 + tid] = make_float4(0.f, 0.f, 0.f, 0.f);
    } else if (b < 1012) {
        ((float4*)g_t)[(b - 762) * 256 + tid] = make_float4(0.f, 0.f, 0.f, 0.f);
    } else {
        for (int i = tid; i < NC; i += 256) g_counts[i] = 0.0f;
        if (tid == 0) g_flag = 0u;
    }
}

// ---------------------------------------------------------------
// K2: fused gram-partials + (argmax -> class scatter).
//  b in [0,320):       G-partial = Xn^T X over 64x64 tile, K-depth 128.
//  b in [320,320+512): warp-per-row argmax + scatter into g_s / g_t.
// ---------------------------------------------------------------
__global__ void k_fused(const float* __restrict__ x,
                        const float* __restrict__ lg) {
    __shared__ float smem[2048];
    int b = blockIdx.x;
    int tid = threadIdx.x;

    if (b < NTILE * NSPLIT) {
        float* As = smem;            // [16][64] : Xn[k][i-tile]
        float* Bs = smem + 1024;     // [16][64] : X [k][j-tile]
        int tile = b >> 5;           // 0..9
        int k0 = (b & 31) * 128;     // split * 128
        int i0 = c_ti[tile] * 64, j0 = c_tj[tile] * 64;
        int tx = tid & 15, ty = tid >> 4;

        float acc[4][4] = {};
#pragma unroll
        for (int kc = 0; kc < 128; kc += 16) {
#pragma unroll
            for (int l = 0; l < 4; l++) {
                int idx = tid + l * 256;          // 0..1023
                int kl = idx >> 6, col = idx & 63;
                int k = k0 + kc + kl;
                As[kl * 64 + col] = g_xn[(size_t)k * CH + i0 + col];
                Bs[kl * 64 + col] = x   [(size_t)k * CH + j0 + col];
            }
            __syncthreads();
            const float4* As4 = (const float4*)As;
            const float4* Bs4 = (const float4*)Bs;
#pragma unroll
            for (int kl = 0; kl < 16; kl++) {
                float4 a = As4[kl * 16 + ty];
                float4 bb = Bs4[kl * 16 + tx];
                acc[0][0] += a.x * bb.x; acc[0][1] += a.x * bb.y;
                acc[0][2] += a.x * bb.z; acc[0][3] += a.x * bb.w;
                acc[1][0] += a.y * bb.x; acc[1][1] += a.y * bb.y;
                acc[1][2] += a.y * bb.z; acc[1][3] += a.y * bb.w;
                acc[2][0] += a.z * bb.x; acc[2][1] += a.z * bb.y;
                acc[2][2] += a.z * bb.z; acc[2][3] += a.z * bb.w;
                acc[3][0] += a.w * bb.x; acc[3][1] += a.w * bb.y;
                acc[3][2] += a.w * bb.z; acc[3][3] += a.w * bb.w;
            }
            __syncthreads();
        }
        float4* p4 = (float4*)(g_part + (size_t)b * 4096);
#pragma unroll
        for (int u = 0; u < 4; u++)
            p4[(ty * 4 + u) * 16 + tx] =
                make_float4(acc[u][0], acc[u][1], acc[u][2], acc[u][3]);
    } else {
        // ---- warp-per-row argmax + scatter, 8 rows per block ----
        int row = ((b - NTILE * NSPLIT) << 3) + (tid >> 5);
        int lane = tid & 31;
        const float4* p = (const float4*)(lg + (size_t)row * NC);  // 250 float4
        float best = -3.4e38f;
        int   bi = 0;
#pragma unroll
        for (int i = 0; i < 8; i++) {
            int idx = lane + (i << 5);
            if (idx < 250) {
                float4 v = p[idx];
                int c = idx << 2;
                if (v.x > best) { best = v.x; bi = c; }
                if (v.y > best) { best = v.y; bi = c + 1; }
                if (v.z > best) { best = v.z; bi = c + 2; }
                if (v.w > best) { best = v.w; bi = c + 3; }
            }
        }
#pragma unroll
        for (int off = 16; off; off >>= 1) {
            float ov = __shfl_xor_sync(0xffffffffu, best, off);
            int   oi = __shfl_xor_sync(0xffffffffu, bi,   off);
            if (ov > best || (ov == best && oi < bi)) { best = ov; bi = oi; }
        }
        int cls = bi;
        float inv = g_invn[row];
        const float4* px = (const float4*)(x + (size_t)row * CH);
#pragma unroll
        for (int j = 0; j < 2; j++) {
            int idx4 = lane + (j << 5);           // 0..63
            float4 xv = px[idx4];
            int base = cls * CH + (idx4 << 2);
            atomicAdd(&g_s[base + 0], xv.x * inv);
            atomicAdd(&g_s[base + 1], xv.y * inv);
            atomicAdd(&g_s[base + 2], xv.z * inv);
            atomicAdd(&g_s[base + 3], xv.w * inv);
            atomicAdd(&g_t[base + 0], xv.x);
            atomicAdd(&g_t[base + 1], xv.y);
            atomicAdd(&g_t[base + 2], xv.z);
            atomicAdd(&g_t[base + 3], xv.w);
        }
        if (lane == 0) atomicAdd(&g_counts[cls], 1.0f);
    }
}

// ---------------------------------------------------------------
// K3: merged redG + proto, single launch (260 blocks x 1024 thr,
// all co-resident: <= 2 blocks/SM x 148 SMs).
//  b in [0,10):   reduce g_part -> g_G (+ mirror), then signal g_flag.
//  b in [10,260): spin on g_flag (redG done), then proto GEMV:
//                 proto_c = (s_c @ G + t_c)/count.
// ---------------------------------------------------------------
__global__ void __launch_bounds__(1024) k_gproto(float* __restrict__ proto) {
    __shared__ float  s_sm[4 * 256];
    __shared__ float4 red[3 * 4 * 64];
    int b = blockIdx.x;
    int tid = threadIdx.x;

    if (b < 10) {
        int idx = b * 1024 + tid;                 // 0..10239
        int tile = idx >> 10;
        int p4i  = idx & 1023;
        int i0 = c_ti[tile] * 64, j0 = c_tj[tile] * 64;

        const float4* part4 = (const float4*)g_part;
        float4 sum = make_float4(0.f, 0.f, 0.f, 0.f);
#pragma unroll 8
        for (int s = 0; s < NSPLIT; s++) {
            float4 v = part4[(size_t)((tile << 5) + s) * 1024 + p4i];
            sum.x += v.x; sum.y += v.y; sum.z += v.z; sum.w += v.w;
        }
        int il = p4i >> 4;
        int jb = (p4i & 15) << 2;
        int i = i0 + il, j = j0 + jb;
        ((float4*)g_G)[(i * CH + j) >> 2] = sum;
        if (i0 != j0) {
            g_G[(j + 0) * CH + i] = sum.x;
            g_G[(j + 1) * CH + i] = sum.y;
            g_G[(j + 2) * CH + i] = sum.z;
            g_G[(j + 3) * CH + i] = sum.w;
        }
        __threadfence();
        __syncthreads();
        if (tid == 0) atomicAdd(&g_flag, 1u);
    } else {
        int c0 = (b - 10) * 4;
        int cgrp = tid >> 8;          // 0..3  class within block
        int sub  = (tid >> 6) & 3;    // k-quarter
        int col4 = tid & 63;          // float4 column group

        s_sm[tid & 1023] = g_s[(size_t)c0 * CH + (tid & 1023)];
        if (tid == 0) {
            while (atomicAdd(&g_flag, 0u) < 10u) { }
        }
        __syncthreads();

        const float4* Gp = (const float4*)g_G + (size_t)(sub * 64) * 64 + col4;
        const float*  sr = s_sm + cgrp * 256 + sub * 64;
        float4 acc = make_float4(0.f, 0.f, 0.f, 0.f);
#pragma unroll
        for (int kb = 0; kb < 64; kb += 8) {
            float4 g0 = Gp[(kb + 0) * 64];
            float4 g1 = Gp[(kb + 1) * 64];
            float4 g2 = Gp[(kb + 2) * 64];
            float4 g3 = Gp[(kb + 3) * 64];
            float4 g4 = Gp[(kb + 4) * 64];
            float4 g5 = Gp[(kb + 5) * 64];
            float4 g6 = Gp[(kb + 6) * 64];
            float4 g7 = Gp[(kb + 7) * 64];
            float s0 = sr[kb + 0], s1 = sr[kb + 1], s2 = sr[kb + 2], s3 = sr[kb + 3];
            float s4 = sr[kb + 4], s5 = sr[kb + 5], s6 = sr[kb + 6], s7 = sr[kb + 7];
            acc.x += s0 * g0.x; acc.y += s0 * g0.y; acc.z += s0 * g0.z; acc.w += s0 * g0.w;
            acc.x += s1 * g1.x; acc.y += s1 * g1.y; acc.z += s1 * g1.z; acc.w += s1 * g1.w;
            acc.x += s2 * g2.x; acc.y += s2 * g2.y; acc.z += s2 * g2.z; acc.w += s2 * g2.w;
            acc.x += s3 * g3.x; acc.y += s3 * g3.y; acc.z += s3 * g3.z; acc.w += s3 * g3.w;
            acc.x += s4 * g4.x; acc.y += s4 * g4.y; acc.z += s4 * g4.z; acc.w += s4 * g4.w;
            acc.x += s5 * g5.x; acc.y += s5 * g5.y; acc.z += s5 * g5.z; acc.w += s5 * g5.w;
            acc.x += s6 * g6.x; acc.y += s6 * g6.y; acc.z += s6 * g6.z; acc.w += s6 * g6.w;
            acc.x += s7 * g7.x; acc.y += s7 * g7.y; acc.z += s7 * g7.z; acc.w += s7 * g7.w;
        }

        if (sub > 0) red[(sub - 1) * 256 + cgrp * 64 + col4] = acc;
        __syncthreads();
        if (sub == 0) {
            float4 o0 = red[0 * 256 + cgrp * 64 + col4];
            float4 o1 = red[1 * 256 + cgrp * 64 + col4];
            float4 o2 = red[2 * 256 + cgrp * 64 + col4];
            acc.x += o0.x + o1.x + o2.x;
            acc.y += o0.y + o1.y + o2.y;
            acc.z += o0.z + o1.z + o2.z;
            acc.w += o0.w + o1.w + o2.w;

            int cls = c0 + cgrp;
            float cnt = g_counts[cls];
            float4 tv = ((const float4*)g_t)[(size_t)cls * 64 + col4];
            float4 v = make_float4(0.f, 0.f, 0.f, 0.f);
            if (cnt > 0.0f) {
                float rc = 1.0f / cnt;
                v = make_float4((acc.x + tv.x) * rc, (acc.y + tv.y) * rc,
                                (acc.z + tv.z) * rc, (acc.w + tv.w) * rc);
            }
            ((float4*)proto)[(size_t)cls * 64 + col4] = v;
        }
    }
}

// ---------------------------------------------------------------
// K4: inter[i][j][:] = proto[j] - proto[i]   (1.02 GB, write-bound)
// ---------------------------------------------------------------
__global__ void k_inter(const float* __restrict__ proto, float* __restrict__ inter) {
    __shared__ float4 pi[16][64];
    __shared__ float4 pj[16][64];
    int i0 = blockIdx.y * 16, j0 = blockIdx.x * 16;
    int tid = threadIdx.x;               // 256 threads

    const float4* p4 = (const float4*)proto;
#pragma unroll
    for (int l = 0; l < 4; l++) {
        int idx = tid + l * 256;         // 0..1023
        int r = idx >> 6, d = idx & 63;
        int gi = i0 + r, gj = j0 + r;
        pi[r][d] = (gi < NC) ? p4[gi * 64 + d] : make_float4(0.f, 0.f, 0.f, 0.f);
        pj[r][d] = (gj < NC) ? p4[gj * 64 + d] : make_float4(0.f, 0.f, 0.f, 0.f);
    }
    __syncthreads();

    int d = tid & 63;
    int p0 = tid >> 6;                   // 0..3
    float4* o4 = (float4*)inter;

    if (i0 + 16 <= NC && j0 + 16 <= NC) {
#pragma unroll 8
        for (int p = p0; p < 256; p += 4) {
            int il = p >> 4, jl = p & 15;
            float4 a = pj[jl][d];
            float4 bv = pi[il][d];
            float4 v = make_float4(a.x - bv.x, a.y - bv.y, a.z - bv.z, a.w - bv.w);
            __stcs(&o4[((size_t)(i0 + il) * NC + (j0 + jl)) * 64 + d], v);
        }
    } else {
        for (int p = p0; p < 256; p += 4) {
            int il = p >> 4, jl = p & 15;
            int i = i0 + il, j = j0 + jl;
            if (i < NC && j < NC) {
                float4 a = pj[jl][d];
                float4 bv = pi[il][d];
                float4 v = make_float4(a.x - bv.x, a.y - bv.y, a.z - bv.z, a.w - bv.w);
                __stcs(&o4[((size_t)i * NC + j) * 64 + d], v);
            }
        }
    }
}

// ---------------------------------------------------------------
extern "C" void kernel_launch(void* const* d_in, const int* in_sizes, int n_in,
                              void* d_out, int out_size) {
    const float* x  = (const float*)d_in[0];   // [4096, 256]
    const float* lg = (const float*)d_in[1];   // [4096, 1000]
    float* out   = (float*)d_out;
    float* proto = out;                         // [1000, 256]
    float* inter = out + (size_t)NC * CH;       // [1000, 1000, 256]

    k_prep  <<<1013, 256>>>(x);
    k_fused <<<NTILE * NSPLIT + 512, 256>>>(x, lg);
    k_gproto<<<260, 1024>>>(proto);
    k_inter <<<dim3(63, 63), 256>>>(proto, inter);
}